// round 5
// baseline (speedup 1.0000x reference)
#include <cuda_runtime.h>
#include <mma.h>
using namespace nvcuda;

// Problem constants: B=8, H=W=128, C=256, NUM_HEADS=8, HD=32, WINDOW=8
#define TOKENS 131072

// Scratch (allocation-free rule: device globals)
__device__ float g_qkv[100663296u];  // [token][3][head][32]
__device__ float g_att[33554432u];   // xt (pre-GEMM1) then att [token][256]
__device__ float g_wq[196608];       // tf32-rounded W_qkv
__device__ float g_wp[65536];        // tf32-rounded W_proj

__device__ __forceinline__ float t32(float x) { return wmma::__float_to_tf32(x); }

__device__ __forceinline__ void cp_async16(void* smem, const void* gmem) {
    unsigned s = (unsigned)__cvta_generic_to_shared(smem);
    asm volatile("cp.async.cg.shared.global [%0], [%1], 16;\n" :: "r"(s), "l"(gmem));
}
__device__ __forceinline__ void cp_commit() { asm volatile("cp.async.commit_group;\n"); }
__device__ __forceinline__ void cp_wait1()  { asm volatile("cp.async.wait_group 1;\n"); }
__device__ __forceinline__ void cp_wait0()  { asm volatile("cp.async.wait_group 0;\n"); }

// ---------------------------------------------------------------------------
// Pre-round inputs to tf32 (RN) once: x -> xt, weights -> g_wq/g_wp.
// ---------------------------------------------------------------------------
__global__ void cvt_inputs(const float* __restrict__ x,
                           const float* __restrict__ wq,
                           const float* __restrict__ wp,
                           float* __restrict__ xt,
                           float* __restrict__ wqt,
                           float* __restrict__ wpt)
{
    const int stride = gridDim.x * blockDim.x;
    const int tid0 = blockIdx.x * blockDim.x + threadIdx.x;
    for (int i = tid0; i < 33554432 / 4; i += stride) {
        float4 v = ((const float4*)x)[i];
        v.x = t32(v.x); v.y = t32(v.y); v.z = t32(v.z); v.w = t32(v.w);
        ((float4*)xt)[i] = v;
    }
    for (int i = tid0; i < (196608 + 65536) / 4; i += stride) {
        if (i < 49152) {
            float4 v = ((const float4*)wq)[i];
            v.x = t32(v.x); v.y = t32(v.y); v.z = t32(v.z); v.w = t32(v.w);
            ((float4*)wqt)[i] = v;
        } else {
            float4 v = ((const float4*)wp)[i - 49152];
            v.x = t32(v.x); v.y = t32(v.y); v.z = t32(v.z); v.w = t32(v.w);
            ((float4*)wpt)[i - 49152] = v;
        }
    }
}

// ---------------------------------------------------------------------------
// TF32 GEMM: C[M,N]=A[M,256]@B[256,N] (+bias). Inputs pre-rounded: NO CVTs.
// BM=BN=128, BK=32, 3-stage cp.async, 1 barrier/tile. 8 warps, 64x32 warp tile.
// smem: 3 stages x (A 128x36 + B 32x132) = 26496 floats = 105984 B, 2 CTA/SM.
// ---------------------------------------------------------------------------
__global__ __launch_bounds__(256, 2) void gemm_wmma(
    const float* __restrict__ A, const float* __restrict__ B,
    const float* __restrict__ bias, float* __restrict__ C, int N)
{
    extern __shared__ float sm[];
    const int tid  = threadIdx.x;
    const int warp = tid >> 5;
    const int lane = tid & 31;
    const int wm = warp >> 2, wn = warp & 3;
    const int bn = blockIdx.x * 128;   // fast dim = cols -> A L2 reuse
    const int bm = blockIdx.y * 128;

    wmma::fragment<wmma::accumulator, 16, 16, 8, float> acc[4][2];
#pragma unroll
    for (int i = 0; i < 4; i++)
#pragma unroll
        for (int j = 0; j < 2; j++) wmma::fill_fragment(acc[i][j], 0.f);

    auto load_tile = [&](int s, int k0) {
        float* As = sm + s * 8832;
        float* Bs = As + 4608;
#pragma unroll
        for (int t = 0; t < 4; t++) {
            int idx = tid + t * 256;                 // 0..1023
            int ar = idx >> 3, ac = (idx & 7) * 4;   // A: 128x32
            cp_async16(&As[ar * 36 + ac], A + (size_t)(bm + ar) * 256 + k0 + ac);
            int br = idx >> 5, bc = (idx & 31) * 4;  // B: 32x128
            cp_async16(&Bs[br * 132 + bc], B + (size_t)(k0 + br) * N + bn + bc);
        }
        cp_commit();
    };

    load_tile(0, 0);
    load_tile(1, 32);
    const int NK = 8;  // 256/32
    for (int kt = 0; kt < NK; kt++) {
        if (kt == NK - 1) cp_wait0(); else cp_wait1();
        __syncthreads();
        if (kt + 2 < NK) load_tile((kt + 2) % 3, (kt + 2) * 32);
        const float* As = sm + (kt % 3) * 8832;
        const float* Bs = As + 4608;
#pragma unroll
        for (int kk = 0; kk < 32; kk += 8) {
            wmma::fragment<wmma::matrix_a, 16, 16, 8, wmma::precision::tf32,
                           wmma::row_major> af[4];
            wmma::fragment<wmma::matrix_b, 16, 16, 8, wmma::precision::tf32,
                           wmma::row_major> bf[2];
#pragma unroll
            for (int i = 0; i < 4; i++)
                wmma::load_matrix_sync(af[i], &As[(wm * 64 + i * 16) * 36 + kk], 36);
#pragma unroll
            for (int j = 0; j < 2; j++)
                wmma::load_matrix_sync(bf[j], &Bs[kk * 132 + wn * 32 + j * 16], 132);
#pragma unroll
            for (int i = 0; i < 4; i++)
#pragma unroll
                for (int j = 0; j < 2; j++)
                    wmma::mma_sync(acc[i][j], af[i], bf[j], acc[i][j]);
        }
    }
    __syncthreads();

    // Epilogue via private smem strip
    float* wb = sm + warp * 320;   // 16 x 20
    const int r = lane >> 1, c0 = (lane & 1) * 8;
#pragma unroll
    for (int i = 0; i < 4; i++) {
#pragma unroll
        for (int j = 0; j < 2; j++) {
            wmma::store_matrix_sync(wb, acc[i][j], 20, wmma::mem_row_major);
            __syncwarp();
            float4 v0 = *(float4*)&wb[r * 20 + c0];
            float4 v1 = *(float4*)&wb[r * 20 + c0 + 4];
            int grow = bm + wm * 64 + i * 16 + r;
            int gcol = bn + wn * 32 + j * 16 + c0;
            if (bias) {
                v0.x += bias[gcol + 0]; v0.y += bias[gcol + 1];
                v0.z += bias[gcol + 2]; v0.w += bias[gcol + 3];
                v1.x += bias[gcol + 4]; v1.y += bias[gcol + 5];
                v1.z += bias[gcol + 6]; v1.w += bias[gcol + 7];
            }
            *(float4*)&C[(size_t)grow * N + gcol]     = v0;
            *(float4*)&C[(size_t)grow * N + gcol + 4] = v1;
            __syncwarp();
        }
    }
}

// ---------------------------------------------------------------------------
// Local window attention (heads 0..3). CTA = 1 window x 2 heads. 256 thr.
// Output written tf32-rounded (feeds proj GEMM without CVT).
// ---------------------------------------------------------------------------
__global__ __launch_bounds__(256, 2) void attn_local_tc(
    const float* __restrict__ qkv, float* __restrict__ att)
{
    extern __shared__ float sm[];
    const int wid = blockIdx.x;
    const int b = wid >> 8, wy = (wid >> 4) & 15, wx = wid & 15;
    const int tid = threadIdx.x;
    const int warp = tid >> 5;
    const int hh = warp >> 2, wl = warp & 3;
    const float scale = 0.17677669529663687f;

#pragma unroll
    for (int i = 0; i < 4; i++) {
        int idx = tid + i * 256;           // 0..1023
        int h2 = idx >> 9;
        int r  = (idx >> 3) & 63;
        int c  = (idx & 7) * 4;
        int hg = (int)blockIdx.y * 2 + h2;
        size_t token = ((size_t)(b * 128 + wy * 8 + (r >> 3))) * 128 + wx * 8 + (r & 7);
        const float* base = qkv + token * 768 + hg * 32 + c;
        float4 q4 = *(const float4*)base;
        float4 k4 = *(const float4*)(base + 256);
        float4 v4 = *(const float4*)(base + 512);
        float* Q = sm + h2 * 11200;
        float* Kt = Q + 2304;
        float* V = Q + 4480;
        Q[r * 36 + c + 0] = t32(q4.x * scale);
        Q[r * 36 + c + 1] = t32(q4.y * scale);
        Q[r * 36 + c + 2] = t32(q4.z * scale);
        Q[r * 36 + c + 3] = t32(q4.w * scale);
        Kt[(c + 0) * 68 + r] = t32(k4.x);
        Kt[(c + 1) * 68 + r] = t32(k4.y);
        Kt[(c + 2) * 68 + r] = t32(k4.z);
        Kt[(c + 3) * 68 + r] = t32(k4.w);
        V[r * 36 + c + 0] = t32(v4.x);
        V[r * 36 + c + 1] = t32(v4.y);
        V[r * 36 + c + 2] = t32(v4.z);
        V[r * 36 + c + 3] = t32(v4.w);
    }
    __syncthreads();

    float* Qh  = sm + hh * 11200;
    float* Kth = Qh + 2304;
    float* Vh  = Qh + 4480;
    float* Sh  = Qh + 6784;

    {   // S = Q @ K^T  (64x64, k=32)
        wmma::fragment<wmma::accumulator, 16, 16, 8, float> accS[4];
#pragma unroll
        for (int j = 0; j < 4; j++) wmma::fill_fragment(accS[j], 0.f);
#pragma unroll
        for (int kk = 0; kk < 32; kk += 8) {
            wmma::fragment<wmma::matrix_a, 16, 16, 8, wmma::precision::tf32,
                           wmma::row_major> af;
            wmma::load_matrix_sync(af, &Qh[(wl * 16) * 36 + kk], 36);
#pragma unroll
            for (int j = 0; j < 4; j++) {
                wmma::fragment<wmma::matrix_b, 16, 16, 8, wmma::precision::tf32,
                               wmma::row_major> bf;
                wmma::load_matrix_sync(bf, &Kth[kk * 68 + j * 16], 68);
                wmma::mma_sync(accS[j], af, bf, accS[j]);
            }
        }
#pragma unroll
        for (int j = 0; j < 4; j++)
            wmma::store_matrix_sync(&Sh[(wl * 16) * 68 + j * 16], accS[j], 68,
                                    wmma::mem_row_major);
    }
    __syncthreads();

    {   // softmax: 2 thr/row
        int h2 = tid >> 7, local = tid & 127;
        int row = local >> 1, half = local & 1;
        float* S = sm + h2 * 11200 + 6784 + row * 68 + half * 32;
        float m = -3.0e38f;
#pragma unroll
        for (int e = 0; e < 32; e++) m = fmaxf(m, S[e]);
        m = fmaxf(m, __shfl_xor_sync(0xffffffffu, m, 1));
        float sum = 0.f;
#pragma unroll
        for (int e = 0; e < 32; e++) {
            float p = __expf(S[e] - m);
            S[e] = t32(p);
            sum += p;
        }
        sum += __shfl_xor_sync(0xffffffffu, sum, 1);
        if (half == 0) (sm + h2 * 11200 + 11136)[row] = 1.f / sum;
    }
    __syncthreads();

    {   // O = P @ V  (64x32, k=64)
        wmma::fragment<wmma::accumulator, 16, 16, 8, float> accO[2];
#pragma unroll
        for (int j = 0; j < 2; j++) wmma::fill_fragment(accO[j], 0.f);
#pragma unroll
        for (int kk = 0; kk < 64; kk += 8) {
            wmma::fragment<wmma::matrix_a, 16, 16, 8, wmma::precision::tf32,
                           wmma::row_major> af;
            wmma::load_matrix_sync(af, &Sh[(wl * 16) * 68 + kk], 68);
#pragma unroll
            for (int j = 0; j < 2; j++) {
                wmma::fragment<wmma::matrix_b, 16, 16, 8, wmma::precision::tf32,
                               wmma::row_major> bf;
                wmma::load_matrix_sync(bf, &Vh[kk * 36 + j * 16], 36);
                wmma::mma_sync(accO[j], af, bf, accO[j]);
            }
        }
#pragma unroll
        for (int j = 0; j < 2; j++)
            wmma::store_matrix_sync(&Qh[(wl * 16) * 36 + j * 16], accO[j], 36,
                                    wmma::mem_row_major);
    }
    __syncthreads();

#pragma unroll
    for (int i = 0; i < 4; i++) {
        int idx = tid + i * 256;
        int h2 = idx >> 9;
        int r  = (idx >> 3) & 63;
        int c  = (idx & 7) * 4;
        int hg = (int)blockIdx.y * 2 + h2;
        float* Q = sm + h2 * 11200;
        float inv = (sm + h2 * 11200 + 11136)[r];
        float4 o = make_float4(t32(Q[r * 36 + c] * inv), t32(Q[r * 36 + c + 1] * inv),
                               t32(Q[r * 36 + c + 2] * inv), t32(Q[r * 36 + c + 3] * inv));
        size_t token = ((size_t)(b * 128 + wy * 8 + (r >> 3))) * 128 + wx * 8 + (r & 7);
        *(float4*)&att[token * 256 + hg * 32 + c] = o;
    }
}

// ---------------------------------------------------------------------------
// Grid (dilated) attention (heads 4..7). CTA = (cell, head); K/V staged ONCE,
// 4 query tiles looped in-CTA. K kept natural [key][dim]; S uses col_major B.
// smem floats: K[256][36]@0, V[256][36]@9216, Q[64][36]@18432,
//              S[64][260]@20736, il[64]@37376 -> 37440 fl = 149760 B.
// ---------------------------------------------------------------------------
__global__ __launch_bounds__(256, 1) void attn_grid_tc(
    const float* __restrict__ qkv, float* __restrict__ att)
{
    extern __shared__ float sm[];
    float* K  = sm;
    float* V  = sm + 9216;
    float* Q  = sm + 18432;
    float* S  = sm + 20736;
    float* il = sm + 37376;

    const int cid = blockIdx.x;
    const int b = cid >> 6, s1 = (cid >> 3) & 7, s2 = cid & 7;
    const int h = 4 + (int)blockIdx.y;
    const int tid = threadIdx.x;
    const int warp = tid >> 5;
    const int wl = warp & 3, wc = warp >> 2;
    const float scale = 0.17677669529663687f;

    // Stage K, V once (256 keys)
#pragma unroll
    for (int i = 0; i < 8; i++) {
        int idx = tid + i * 256;           // 0..2047
        int rk = idx >> 3, c = (idx & 7) * 4;
        size_t ktok = ((size_t)(b * 128 + (rk >> 4) * 8 + s1)) * 128 + (rk & 15) * 8 + s2;
        const float* base = qkv + ktok * 768 + h * 32 + c;
        float4 k4 = *(const float4*)(base + 256);
        float4 v4 = *(const float4*)(base + 512);
        K[rk * 36 + c + 0] = t32(k4.x);
        K[rk * 36 + c + 1] = t32(k4.y);
        K[rk * 36 + c + 2] = t32(k4.z);
        K[rk * 36 + c + 3] = t32(k4.w);
        V[rk * 36 + c + 0] = t32(v4.x);
        V[rk * 36 + c + 1] = t32(v4.y);
        V[rk * 36 + c + 2] = t32(v4.z);
        V[rk * 36 + c + 3] = t32(v4.w);
    }

    for (int qt = 0; qt < 4; qt++) {
        __syncthreads();   // K/V staged (qt=0); Q strip free of prev O (qt>0)
        // Stage Q tile (64 queries)
#pragma unroll
        for (int i = 0; i < 2; i++) {
            int idx = tid + i * 256;       // 0..511
            int r = idx >> 3, c = (idx & 7) * 4;
            int qq = qt * 64 + r;
            size_t token = ((size_t)(b * 128 + (qq >> 4) * 8 + s1)) * 128 + (qq & 15) * 8 + s2;
            float4 q4 = *(const float4*)(qkv + token * 768 + h * 32 + c);
            Q[r * 36 + c + 0] = t32(q4.x * scale);
            Q[r * 36 + c + 1] = t32(q4.y * scale);
            Q[r * 36 + c + 2] = t32(q4.z * scale);
            Q[r * 36 + c + 3] = t32(q4.w * scale);
        }
        __syncthreads();

        // S = Q @ K^T (64x256, k=32); B loaded col_major from natural K layout
        {
            wmma::fragment<wmma::matrix_a, 16, 16, 8, wmma::precision::tf32,
                           wmma::row_major> af[4];
#pragma unroll
            for (int ki = 0; ki < 4; ki++)
                wmma::load_matrix_sync(af[ki], &Q[(wl * 16) * 36 + ki * 8], 36);
            for (int j = wc * 8; j < wc * 8 + 8; j++) {
                wmma::fragment<wmma::accumulator, 16, 16, 8, float> acc;
                wmma::fill_fragment(acc, 0.f);
#pragma unroll
                for (int ki = 0; ki < 4; ki++) {
                    wmma::fragment<wmma::matrix_b, 16, 16, 8, wmma::precision::tf32,
                                   wmma::col_major> bf;
                    wmma::load_matrix_sync(bf, &K[(j * 16) * 36 + ki * 8], 36);
                    wmma::mma_sync(acc, af[ki], bf, acc);
                }
                wmma::store_matrix_sync(&S[(wl * 16) * 260 + j * 16], acc, 260,
                                        wmma::mem_row_major);
            }
        }
        __syncthreads();

        // Softmax: 4 thr/row
        {
            int row = tid >> 2, quarter = tid & 3;
            float* Sp = S + row * 260 + quarter * 64;
            float m = -3.0e38f;
#pragma unroll
            for (int e = 0; e < 64; e++) m = fmaxf(m, Sp[e]);
            m = fmaxf(m, __shfl_xor_sync(0xffffffffu, m, 1));
            m = fmaxf(m, __shfl_xor_sync(0xffffffffu, m, 2));
            float sum = 0.f;
#pragma unroll
            for (int e = 0; e < 64; e++) {
                float p = __expf(Sp[e] - m);
                Sp[e] = t32(p);
                sum += p;
            }
            sum += __shfl_xor_sync(0xffffffffu, sum, 1);
            sum += __shfl_xor_sync(0xffffffffu, sum, 2);
            if (quarter == 0) il[row] = 1.f / sum;
        }
        __syncthreads();

        // O = P @ V (64x32, k=256) -> store into Q strip
        {
            wmma::fragment<wmma::accumulator, 16, 16, 8, float> acc;
            wmma::fill_fragment(acc, 0.f);
#pragma unroll 4
            for (int ks = 0; ks < 32; ks++) {
                int kk = ks * 8;
                wmma::fragment<wmma::matrix_a, 16, 16, 8, wmma::precision::tf32,
                               wmma::row_major> af;
                wmma::fragment<wmma::matrix_b, 16, 16, 8, wmma::precision::tf32,
                               wmma::row_major> bf;
                wmma::load_matrix_sync(af, &S[(wl * 16) * 260 + kk], 260);
                wmma::load_matrix_sync(bf, &V[kk * 36 + wc * 16], 36);
                wmma::mma_sync(acc, af, bf, acc);
            }
            wmma::store_matrix_sync(&Q[(wl * 16) * 36 + wc * 16], acc, 36,
                                    wmma::mem_row_major);
        }
        __syncthreads();

        // Write out tf32-rounded
#pragma unroll
        for (int i = 0; i < 2; i++) {
            int idx = tid + i * 256;
            int r = idx >> 3, c = (idx & 7) * 4;
            float inv = il[r];
            float4 o = make_float4(t32(Q[r * 36 + c] * inv), t32(Q[r * 36 + c + 1] * inv),
                                   t32(Q[r * 36 + c + 2] * inv), t32(Q[r * 36 + c + 3] * inv));
            int qq = qt * 64 + r;
            size_t token = ((size_t)(b * 128 + (qq >> 4) * 8 + s1)) * 128 + (qq & 15) * 8 + s2;
            *(float4*)&att[token * 256 + h * 32 + c] = o;
        }
    }
}

// ---------------------------------------------------------------------------
extern "C" void kernel_launch(void* const* d_in, const int* in_sizes, int n_in,
                              void* d_out, int out_size)
{
    (void)in_sizes; (void)n_in; (void)out_size;
    const float* x     = (const float*)d_in[0];
    const float* Wqkv  = (const float*)d_in[1];
    const float* Wproj = (const float*)d_in[2];
    const float* bproj = (const float*)d_in[3];
    float* out = (float*)d_out;

    float *qkv = nullptr, *att = nullptr, *wq = nullptr, *wp = nullptr;
    cudaGetSymbolAddress((void**)&qkv, g_qkv);
    cudaGetSymbolAddress((void**)&att, g_att);
    cudaGetSymbolAddress((void**)&wq,  g_wq);
    cudaGetSymbolAddress((void**)&wp,  g_wp);

    cudaFuncSetAttribute(gemm_wmma, cudaFuncAttributeMaxDynamicSharedMemorySize, 105984);
    cudaFuncSetAttribute(attn_local_tc, cudaFuncAttributeMaxDynamicSharedMemorySize, 89600);
    cudaFuncSetAttribute(attn_grid_tc, cudaFuncAttributeMaxDynamicSharedMemorySize, 149760);

    // 0) pre-round x (into g_att, free until attention) and weights to tf32
    cvt_inputs<<<4096, 256>>>(x, Wqkv, Wproj, att, wq, wp);
    // 1) QKV = xt @ W_qkv
    gemm_wmma<<<dim3(6, 1024), 256, 105984>>>(att, wq, nullptr, qkv, 768);
    // 2) local window attention (heads 0..3) — overwrites g_att with att
    attn_local_tc<<<dim3(2048, 2), 256, 89600>>>(qkv, att);
    // 3) dilated grid attention (heads 4..7)
    attn_grid_tc<<<dim3(512, 4), 256, 149760>>>(qkv, att);
    // 4) out = att @ W_proj + b_proj
    gemm_wmma<<<dim3(2, 1024), 256, 105984>>>(att, wp, bproj, out, 256);
}